// round 4
// baseline (speedup 1.0000x reference)
#include <cuda_runtime.h>
#include <cuda_bf16.h>
#include <cstdint>
#include <cstddef>

#define BSZ   4
#define CDIM  128
#define CQD   16
#define NPOS  4096
#define OUT_OFF (BSZ*CDIM*NPOS)   /* 2097152 floats; attention follows */

// ----------------- device scratch (no allocation allowed) -------------------
__device__ float g_q[BSZ*NPOS*CQD];                 // [b][n][d]
__device__ float g_k[BSZ*NPOS*CQD];                 // [b][n][d]  (k[b,d,n] stored n-major rows)
__device__ float g_v[(size_t)BSZ*CDIM*NPOS];        // [b][c][n]
__device__ float g_Spart[BSZ*4*NPOS];               // [b][g][n] partial rowsums
__device__ float g_Vpart[(size_t)BSZ*4*CDIM*NPOS];  // [b][g][c][n] partial PV

// ----------------- helpers ---------------------------------------------------
__device__ __forceinline__ unsigned f2tf(float f) {
    unsigned r;
    asm("cvt.rna.tf32.f32 %0, %1;" : "=r"(r) : "f"(f));
    return r;
}

__device__ __forceinline__ void mma_tf32(float c[4],
                                         unsigned a0, unsigned a1, unsigned a2, unsigned a3,
                                         unsigned b0, unsigned b1) {
    asm volatile(
        "mma.sync.aligned.m16n8k8.row.col.f32.tf32.tf32.f32 "
        "{%0,%1,%2,%3},{%4,%5,%6,%7},{%8,%9},{%0,%1,%2,%3};"
        : "+f"(c[0]), "+f"(c[1]), "+f"(c[2]), "+f"(c[3])
        : "r"(a0), "r"(a1), "r"(a2), "r"(a3), "r"(b0), "r"(b1));
}

// decode work item -> (r, g), items ordered by r DESCENDING for load balance
__device__ __forceinline__ void decode_item(int item, int& r, int& g) {
    r = 63; g = item;
    while (true) {
        int ng = (r >> 4) + 1;
        if (g < ng) break;
        g -= ng; r--;
    }
}

// ======================= K1: q,k projection (fp32) ===========================
// q[b,n,d] = sum_c wq[d,c] x[b,c,n] + bq[d];  k same with wk,bk.
__global__ void __launch_bounds__(256) qk_proj(
    const float* __restrict__ x,
    const float* __restrict__ wq, const float* __restrict__ bq,
    const float* __restrict__ wk, const float* __restrict__ bk)
{
    __shared__ float wqs[CQD*CDIM], wks[CQD*CDIM];
    int tid = threadIdx.x;
    for (int i = tid; i < CQD*CDIM; i += 256) { wqs[i] = wq[i]; wks[i] = wk[i]; }
    __syncthreads();

    int t = blockIdx.x * 256 + tid;          // 0 .. B*N-1
    int b = t >> 12;
    int n = t & (NPOS - 1);
    const float* xb = x + (size_t)b*CDIM*NPOS + n;

    float qa[CQD], ka[CQD];
#pragma unroll
    for (int d = 0; d < CQD; d++) { qa[d] = bq[d]; ka[d] = bk[d]; }

    for (int c = 0; c < CDIM; c++) {
        float xv = xb[(size_t)c * NPOS];
#pragma unroll
        for (int d = 0; d < CQD; d++) {
            qa[d] = fmaf(wqs[d*CDIM + c], xv, qa[d]);
            ka[d] = fmaf(wks[d*CDIM + c], xv, ka[d]);
        }
    }
    float* qo = g_q + (size_t)t * CQD;
    float* ko = g_k + (size_t)t * CQD;
#pragma unroll
    for (int d = 0; d < CQD; d++) { qo[d] = qa[d]; ko[d] = ka[d]; }
}

// ======================= K2: v projection (tf32 MMA) =========================
// v[b,c,n] = sum_c' wv[c,c'] x[b,c',n] + bv[c]
// Block: 64 n-columns, all 128 c; 8 warps, each warp: 16 c x 64 n.
__global__ void __launch_bounds__(256) v_proj(
    const float* __restrict__ x,
    const float* __restrict__ wv, const float* __restrict__ bv)
{
    int b  = blockIdx.x >> 6;
    int n0 = (blockIdx.x & 63) << 6;
    int w    = threadIdx.x >> 5;
    int lane = threadIdx.x & 31;
    int gq   = lane >> 2;
    int tig  = lane & 3;
    int cb   = w << 4;

    float acc[8][4];
    {
        float blo = bv[cb + gq], bhi = bv[cb + gq + 8];
#pragma unroll
        for (int nt = 0; nt < 8; nt++) {
            acc[nt][0] = blo; acc[nt][1] = blo;
            acc[nt][2] = bhi; acc[nt][3] = bhi;
        }
    }

    const float* xb = x + (size_t)b*CDIM*NPOS;
    for (int k0 = 0; k0 < CDIM; k0 += 8) {
        unsigned a0 = f2tf(wv[(cb+gq  )*CDIM + k0 + tig    ]);
        unsigned a1 = f2tf(wv[(cb+gq+8)*CDIM + k0 + tig    ]);
        unsigned a2 = f2tf(wv[(cb+gq  )*CDIM + k0 + tig + 4]);
        unsigned a3 = f2tf(wv[(cb+gq+8)*CDIM + k0 + tig + 4]);
#pragma unroll
        for (int nt = 0; nt < 8; nt++) {
            unsigned b0 = f2tf(xb[(size_t)(k0+tig  )*NPOS + n0 + nt*8 + gq]);
            unsigned b1 = f2tf(xb[(size_t)(k0+tig+4)*NPOS + n0 + nt*8 + gq]);
            mma_tf32(acc[nt], a0, a1, a2, a3, b0, b1);
        }
    }

    float* vb = g_v + (size_t)b*CDIM*NPOS;
#pragma unroll
    for (int nt = 0; nt < 8; nt++) {
        int n = n0 + nt*8 + tig*2;
        *(float2*)&vb[(size_t)(cb+gq  )*NPOS + n] = make_float2(acc[nt][0], acc[nt][1]);
        *(float2*)&vb[(size_t)(cb+gq+8)*NPOS + n] = make_float2(acc[nt][2], acc[nt][3]);
    }
}

// ======================= K3: rowsum pass =====================================
// Block handles (b, r, g): rows [r*64, r*64+64), cols [g*1024, min(L,(g+1)*1024)).
__global__ void __launch_bounds__(256) rowsum_k()
{
    int b = blockIdx.x & 3;
    int item = blockIdx.x >> 2;
    int r, g; decode_item(item, r, g);

    int tid = threadIdx.x;
    int i  = tid >> 2;
    int jq = tid & 3;
    int i0 = r << 6;
    int col0 = g << 10;
    int colEnd = min((r + 1) << 6, col0 + 1024);
    int nt = (colEnd - col0) >> 6;

    const float4* qrow = (const float4*)(g_q + ((size_t)(b << 12) + i0 + i) * CQD);
    float4 q0 = qrow[0], q1 = qrow[1], q2 = qrow[2], q3 = qrow[3];

    __shared__ float ks[64 * 20];  // padded rows (80B stride: conflict-free)
    float rsum = 0.f;

    for (int t = 0; t < nt; t++) {
        __syncthreads();
        {
            const float4 kv = ((const float4*)(g_k +
                ((size_t)(b << 12) + col0 + t*64 + (tid >> 2)) * CQD))[tid & 3];
            *(float4*)&ks[(tid >> 2) * 20 + (tid & 3) * 4] = kv;
        }
        __syncthreads();
#pragma unroll
        for (int jj = 0; jj < 16; jj++) {
            int j = jj * 4 + jq;
            const float4* kr = (const float4*)&ks[j * 20];
            float4 k0 = kr[0], k1 = kr[1], k2 = kr[2], k3 = kr[3];
            float e = q0.x*k0.x + q0.y*k0.y + q0.z*k0.z + q0.w*k0.w
                    + q1.x*k1.x + q1.y*k1.y + q1.z*k1.z + q1.w*k1.w
                    + q2.x*k2.x + q2.y*k2.y + q2.z*k2.z + q2.w*k2.w
                    + q3.x*k3.x + q3.y*k3.y + q3.z*k3.z + q3.w*k3.w;
            rsum += __expf(e);
        }
    }

    rsum += __shfl_xor_sync(0xffffffffu, rsum, 1);
    rsum += __shfl_xor_sync(0xffffffffu, rsum, 2);
    if (jq == 0)
        g_Spart[(((size_t)b*4 + g) << 12) + i0 + i] = rsum;
}

// ======================= K5: main pass =======================================
// Recompute e, write normalized p to attention output, accumulate PV via tf32 MMA.
__global__ void __launch_bounds__(256, 2) attn_main(float* __restrict__ out)
{
    int b = blockIdx.x & 3;
    int item = blockIdx.x >> 2;
    int r, g; decode_item(item, r, g);

    int tid = threadIdx.x;
    int i  = tid >> 2;
    int jq = tid & 3;
    int i0 = r << 6;
    int col0 = g << 10;
    int colEnd = min((r + 1) << 6, col0 + 1024);
    int nt = (colEnd - col0) >> 6;
    int ngg = (r >> 4) + 1;

    __shared__ float ks[64 * 20];
    __shared__ float ps[64 * 68];   // pad 68: stride 272B -> conflict-free frag reads
    __shared__ float sinv[64];

    if (tid < 64) {
        float s = 0.f;
        for (int gg = 0; gg < ngg; gg++)
            s += g_Spart[(((size_t)b*4 + gg) << 12) + i0 + tid];
        sinv[tid] = 1.0f / s;
    }
    __syncthreads();
    float inv_i = sinv[i];

    const float4* qrow = (const float4*)(g_q + ((size_t)(b << 12) + i0 + i) * CQD);
    float4 q0 = qrow[0], q1 = qrow[1], q2 = qrow[2], q3 = qrow[3];

    int w    = tid >> 5;
    int lane = tid & 31;
    int gq   = lane >> 2;
    int tig  = lane & 3;
    int cb   = w << 4;

    float acc[8][4];
#pragma unroll
    for (int a = 0; a < 8; a++)
#pragma unroll
        for (int c = 0; c < 4; c++) acc[a][c] = 0.f;

    float* attnb = out + OUT_OFF + ((size_t)b << 24);   // b * N * N

    for (int t = 0; t < nt; t++) {
        __syncthreads();
        {
            const float4 kv = ((const float4*)(g_k +
                ((size_t)(b << 12) + col0 + t*64 + (tid >> 2)) * CQD))[tid & 3];
            *(float4*)&ks[(tid >> 2) * 20 + (tid & 3) * 4] = kv;
        }
        __syncthreads();

#pragma unroll
        for (int jj = 0; jj < 16; jj++) {
            int j = jj * 4 + jq;
            const float4* kr = (const float4*)&ks[j * 20];
            float4 k0 = kr[0], k1 = kr[1], k2 = kr[2], k3 = kr[3];
            float e = q0.x*k0.x + q0.y*k0.y + q0.z*k0.z + q0.w*k0.w
                    + q1.x*k1.x + q1.y*k1.y + q1.z*k1.z + q1.w*k1.w
                    + q2.x*k2.x + q2.y*k2.y + q2.z*k2.z + q2.w*k2.w
                    + q3.x*k3.x + q3.y*k3.y + q3.z*k3.z + q3.w*k3.w;
            ps[i * 68 + j] = __expf(e) * inv_i;
        }
        __syncthreads();

        // coalesced write of the p tile to the attention output
        int jcol0 = col0 + t * 64;
#pragma unroll
        for (int w2 = 0; w2 < 16; w2++) {
            int idx = w2 * 256 + tid;            // 0..4095
            int ii  = idx >> 6;
            int jj2 = idx & 63;
            attnb[(size_t)(i0 + ii) * NPOS + jcol0 + jj2] = ps[ii * 68 + jj2];
        }

        // PV accumulate: D[c][i] += v[c][m] * p[i][m]  (tf32 MMA, A from gmem, B from smem)
        const float* vbase = g_v + (size_t)b*CDIM*NPOS + jcol0;
#pragma unroll
        for (int k8 = 0; k8 < 8; k8++) {
            int m = k8 * 8;
            unsigned a0 = f2tf(vbase[(size_t)(cb+gq  )*NPOS + m + tig    ]);
            unsigned a1 = f2tf(vbase[(size_t)(cb+gq+8)*NPOS + m + tig    ]);
            unsigned a2 = f2tf(vbase[(size_t)(cb+gq  )*NPOS + m + tig + 4]);
            unsigned a3 = f2tf(vbase[(size_t)(cb+gq+8)*NPOS + m + tig + 4]);
#pragma unroll
            for (int ntile = 0; ntile < 8; ntile++) {
                unsigned b0 = f2tf(ps[(ntile*8 + gq) * 68 + m + tig    ]);
                unsigned b1 = f2tf(ps[(ntile*8 + gq) * 68 + m + tig + 4]);
                mma_tf32(acc[ntile], a0, a1, a2, a3, b0, b1);
            }
        }
    }

    // store partial PV: g_Vpart[b][g][c][i0+i]
    float* vp = g_Vpart + (((size_t)b*4 + g) * CDIM) * NPOS;
#pragma unroll
    for (int ntile = 0; ntile < 8; ntile++) {
        int irow = i0 + ntile*8 + tig*2;
        *(float2*)&vp[(size_t)(cb+gq  )*NPOS + irow] = make_float2(acc[ntile][0], acc[ntile][1]);
        *(float2*)&vp[(size_t)(cb+gq+8)*NPOS + irow] = make_float2(acc[ntile][2], acc[ntile][3]);
    }
}

// ======================= K6: zero-fill masked attention ======================
__global__ void __launch_bounds__(128) zerofill(float* __restrict__ out)
{
    int row = blockIdx.x;                 // 0 .. B*N-1
    int n   = row & (NPOS - 1);
    int L   = ((n >> 6) + 1) << 6;
    if (L >= NPOS) return;
    float4* dst = (float4*)(out + OUT_OFF + ((size_t)row << 12) + L);
    int cnt4 = (NPOS - L) >> 2;
    float4 z = make_float4(0.f, 0.f, 0.f, 0.f);
    for (int t = threadIdx.x; t < cnt4; t += 128) dst[t] = z;
}

// ======================= K7: finalize ========================================
// out[b,c,n] = gamma * sum_g Vpart[b][g][c][n] + x[b,c,n]
__global__ void __launch_bounds__(256) finalize(
    const float* __restrict__ x, const float* __restrict__ gamma,
    float* __restrict__ out)
{
    int t = blockIdx.x * 256 + threadIdx.x;    // < B*C*N
    int n  = t & (NPOS - 1);
    int bc = t >> 12;                           // b*128 + c
    int b  = bc >> 7;
    int c  = bc & 127;
    int ngg = (n >> 10) + 1;

    const float* vp = g_Vpart + ((size_t)(b*4) * CDIM + c) * NPOS + n;
    float s = 0.f;
    for (int gg = 0; gg < ngg; gg++)
        s += vp[(size_t)gg * CDIM * NPOS];
    out[t] = gamma[0] * s + x[t];
}

// ======================= launch ==============================================
extern "C" void kernel_launch(void* const* d_in, const int* in_sizes, int n_in,
                              void* d_out, int out_size)
{
    const float* x     = (const float*)d_in[0];
    const float* wq    = (const float*)d_in[1];
    const float* bq    = (const float*)d_in[2];
    const float* wk    = (const float*)d_in[3];
    const float* bk    = (const float*)d_in[4];
    const float* wv    = (const float*)d_in[5];
    const float* bv    = (const float*)d_in[6];
    const float* gamma = (const float*)d_in[7];
    float* out = (float*)d_out;

    qk_proj<<<BSZ*NPOS/256, 256>>>(x, wq, bq, wk, bk);
    v_proj<<<BSZ*(NPOS/64), 256>>>(x, wv, bv);
    rowsum_k<<<BSZ*160, 256>>>();
    attn_main<<<BSZ*160, 256>>>(out);
    zerofill<<<BSZ*NPOS, 128>>>(out);
    finalize<<<(BSZ*CDIM*NPOS)/256, 256>>>(x, gamma, out);
}

// round 7
// speedup vs baseline: 1.2886x; 1.2886x over previous
#include <cuda_runtime.h>
#include <cuda_bf16.h>
#include <cstdint>
#include <cstddef>

#define BSZ   4
#define CDIM  128
#define CQD   16
#define NPOS  4096
#define OUT_OFF (BSZ*CDIM*NPOS)   /* 2097152 floats; attention follows */

// ----------------- device scratch (no allocation allowed) -------------------
__device__ float          g_q[BSZ*NPOS*CQD];                 // [b][n][d]
__device__ float          g_k[BSZ*NPOS*CQD];                 // [b][n][d]
__device__ __nv_bfloat16  g_v[(size_t)BSZ*CDIM*NPOS];        // [b][c][n] bf16
__device__ float          g_Spart[BSZ*4*NPOS];               // [b][g][n] partial rowsums
__device__ float          g_Vpart[(size_t)BSZ*4*CDIM*NPOS];  // [b][g][c][n] partial PV

// ----------------- helpers ---------------------------------------------------
__device__ __forceinline__ unsigned f2tf(float f) {
    unsigned r;
    asm("cvt.rna.tf32.f32 %0, %1;" : "=r"(r) : "f"(f));
    return r;
}

__device__ __forceinline__ void mma_tf32(float c[4],
                                         unsigned a0, unsigned a1, unsigned a2, unsigned a3,
                                         unsigned b0, unsigned b1) {
    asm volatile(
        "mma.sync.aligned.m16n8k8.row.col.f32.tf32.tf32.f32 "
        "{%0,%1,%2,%3},{%4,%5,%6,%7},{%8,%9},{%0,%1,%2,%3};"
        : "+f"(c[0]), "+f"(c[1]), "+f"(c[2]), "+f"(c[3])
        : "r"(a0), "r"(a1), "r"(a2), "r"(a3), "r"(b0), "r"(b1));
}

__device__ __forceinline__ void mma_bf16(float c[4],
                                         unsigned a0, unsigned a1, unsigned a2, unsigned a3,
                                         unsigned b0, unsigned b1) {
    asm volatile(
        "mma.sync.aligned.m16n8k16.row.col.f32.bf16.bf16.f32 "
        "{%0,%1,%2,%3},{%4,%5,%6,%7},{%8,%9},{%0,%1,%2,%3};"
        : "+f"(c[0]), "+f"(c[1]), "+f"(c[2]), "+f"(c[3])
        : "r"(a0), "r"(a1), "r"(a2), "r"(a3), "r"(b0), "r"(b1));
}

__device__ __forceinline__ void ldsm_x4(unsigned& r0, unsigned& r1,
                                        unsigned& r2, unsigned& r3, unsigned addr) {
    asm volatile("ldmatrix.sync.aligned.m8n8.x4.shared.b16 {%0,%1,%2,%3}, [%4];"
                 : "=r"(r0), "=r"(r1), "=r"(r2), "=r"(r3) : "r"(addr));
}

// decode work item -> (r, g), items ordered by r DESCENDING for load balance
__device__ __forceinline__ void decode_item(int item, int& r, int& g) {
    r = 63; g = item;
    while (true) {
        int ng = (r >> 4) + 1;
        if (g < ng) break;
        g -= ng; r--;
    }
}

// ======================= K1: q,k projection (fp32) ===========================
__global__ void __launch_bounds__(256) qk_proj(
    const float* __restrict__ x,
    const float* __restrict__ wq, const float* __restrict__ bq,
    const float* __restrict__ wk, const float* __restrict__ bk)
{
    __shared__ float wqs[CQD*CDIM], wks[CQD*CDIM];
    int tid = threadIdx.x;
    for (int i = tid; i < CQD*CDIM; i += 256) { wqs[i] = wq[i]; wks[i] = wk[i]; }
    __syncthreads();

    int t = blockIdx.x * 256 + tid;          // 0 .. B*N-1
    int b = t >> 12;
    int n = t & (NPOS - 1);
    const float* xb = x + (size_t)b*CDIM*NPOS + n;

    float qa[CQD], ka[CQD];
#pragma unroll
    for (int d = 0; d < CQD; d++) { qa[d] = bq[d]; ka[d] = bk[d]; }

    for (int c = 0; c < CDIM; c++) {
        float xv = xb[(size_t)c * NPOS];
#pragma unroll
        for (int d = 0; d < CQD; d++) {
            qa[d] = fmaf(wqs[d*CDIM + c], xv, qa[d]);
            ka[d] = fmaf(wks[d*CDIM + c], xv, ka[d]);
        }
    }
    float* qo = g_q + (size_t)t * CQD;
    float* ko = g_k + (size_t)t * CQD;
#pragma unroll
    for (int d = 0; d < CQD; d++) { qo[d] = qa[d]; ko[d] = ka[d]; }
}

// ======================= K2: v projection (tf32 MMA, bf16 out) ===============
__global__ void __launch_bounds__(256) v_proj(
    const float* __restrict__ x,
    const float* __restrict__ wv, const float* __restrict__ bv)
{
    int b  = blockIdx.x >> 6;
    int n0 = (blockIdx.x & 63) << 6;
    int w    = threadIdx.x >> 5;
    int lane = threadIdx.x & 31;
    int gq   = lane >> 2;
    int tig  = lane & 3;
    int cb   = w << 4;

    float acc[8][4];
    {
        float blo = bv[cb + gq], bhi = bv[cb + gq + 8];
#pragma unroll
        for (int nt = 0; nt < 8; nt++) {
            acc[nt][0] = blo; acc[nt][1] = blo;
            acc[nt][2] = bhi; acc[nt][3] = bhi;
        }
    }

    const float* xb = x + (size_t)b*CDIM*NPOS;
    for (int k0 = 0; k0 < CDIM; k0 += 8) {
        unsigned a0 = f2tf(wv[(cb+gq  )*CDIM + k0 + tig    ]);
        unsigned a1 = f2tf(wv[(cb+gq+8)*CDIM + k0 + tig    ]);
        unsigned a2 = f2tf(wv[(cb+gq  )*CDIM + k0 + tig + 4]);
        unsigned a3 = f2tf(wv[(cb+gq+8)*CDIM + k0 + tig + 4]);
#pragma unroll
        for (int nt = 0; nt < 8; nt++) {
            unsigned b0 = f2tf(xb[(size_t)(k0+tig  )*NPOS + n0 + nt*8 + gq]);
            unsigned b1 = f2tf(xb[(size_t)(k0+tig+4)*NPOS + n0 + nt*8 + gq]);
            mma_tf32(acc[nt], a0, a1, a2, a3, b0, b1);
        }
    }

    __nv_bfloat16* vb = g_v + (size_t)b*CDIM*NPOS;
#pragma unroll
    for (int nt = 0; nt < 8; nt++) {
        int n = n0 + nt*8 + tig*2;
        *(__nv_bfloat162*)&vb[(size_t)(cb+gq  )*NPOS + n] =
            __float22bfloat162_rn(make_float2(acc[nt][0], acc[nt][1]));
        *(__nv_bfloat162*)&vb[(size_t)(cb+gq+8)*NPOS + n] =
            __float22bfloat162_rn(make_float2(acc[nt][2], acc[nt][3]));
    }
}

// ======================= K3: rowsum pass =====================================
__global__ void __launch_bounds__(256) rowsum_k()
{
    int b = blockIdx.x & 3;
    int item = blockIdx.x >> 2;
    int r, g; decode_item(item, r, g);

    int tid = threadIdx.x;
    int i  = tid >> 2;
    int jq = tid & 3;
    int i0 = r << 6;
    int col0 = g << 10;
    int colEnd = min((r + 1) << 6, col0 + 1024);
    int nt = (colEnd - col0) >> 6;

    const float4* qrow = (const float4*)(g_q + ((size_t)(b << 12) + i0 + i) * CQD);
    float4 q0 = qrow[0], q1 = qrow[1], q2 = qrow[2], q3 = qrow[3];

    __shared__ float ks[64 * 20];
    float rsum = 0.f;

    for (int t = 0; t < nt; t++) {
        __syncthreads();
        {
            const float4 kv = ((const float4*)(g_k +
                ((size_t)(b << 12) + col0 + t*64 + (tid >> 2)) * CQD))[tid & 3];
            *(float4*)&ks[(tid >> 2) * 20 + (tid & 3) * 4] = kv;
        }
        __syncthreads();
#pragma unroll
        for (int jj = 0; jj < 16; jj++) {
            int j = jj * 4 + jq;
            const float4* kr = (const float4*)&ks[j * 20];
            float4 k0 = kr[0], k1 = kr[1], k2 = kr[2], k3 = kr[3];
            float e = q0.x*k0.x + q0.y*k0.y + q0.z*k0.z + q0.w*k0.w
                    + q1.x*k1.x + q1.y*k1.y + q1.z*k1.z + q1.w*k1.w
                    + q2.x*k2.x + q2.y*k2.y + q2.z*k2.z + q2.w*k2.w
                    + q3.x*k3.x + q3.y*k3.y + q3.z*k3.z + q3.w*k3.w;
            rsum += __expf(e);
        }
    }

    rsum += __shfl_xor_sync(0xffffffffu, rsum, 1);
    rsum += __shfl_xor_sync(0xffffffffu, rsum, 2);
    if (jq == 0)
        g_Spart[(((size_t)b*4 + g) << 12) + i0 + i] = rsum;
}

// ======================= K5: main pass (bf16 MMA + ldmatrix) =================
// dynamic smem layout (all row strides 144B -> LDSM conflict-free):
//   ks   : 64*20 fp32          (5120 B)
//   psm  : 64*68 fp32          (17408 B)
//   vsm  : 128*72 bf16         (18432 B)
//   pbm  : 64*72 bf16          (9216 B)
//   sinv : 64 fp32             (256 B)
#define ATTN_SMEM (5120 + 17408 + 18432 + 9216 + 256)

__global__ void __launch_bounds__(256, 2) attn_main(float* __restrict__ out)
{
    extern __shared__ char smem_raw[];
    float*          ks   = (float*)smem_raw;
    float*          psm  = ks + 64*20;
    __nv_bfloat16*  vsm  = (__nv_bfloat16*)(psm + 64*68);
    __nv_bfloat16*  pbm  = vsm + 128*72;
    float*          sinv = (float*)(pbm + 64*72);

    int b = blockIdx.x & 3;
    int item = blockIdx.x >> 2;
    int r, g; decode_item(item, r, g);

    int tid = threadIdx.x;
    int i  = tid >> 2;
    int jq = tid & 3;
    int i0 = r << 6;
    int col0 = g << 10;
    int colEnd = min((r + 1) << 6, col0 + 1024);
    int nt = (colEnd - col0) >> 6;
    int ngg = (r >> 4) + 1;

    if (tid < 64) {
        float s = 0.f;
        for (int gg = 0; gg < ngg; gg++)
            s += g_Spart[(((size_t)b*4 + gg) << 12) + i0 + tid];
        sinv[tid] = 1.0f / s;
    }
    __syncthreads();
    float inv_i = sinv[i];

    const float4* qrow = (const float4*)(g_q + ((size_t)(b << 12) + i0 + i) * CQD);
    float4 q0 = qrow[0], q1 = qrow[1], q2 = qrow[2], q3 = qrow[3];

    int w    = tid >> 5;
    int lane = tid & 31;
    int cb   = w << 4;

    // ldmatrix base addresses (u32 shared-space)
    unsigned vsm_sh = (unsigned)__cvta_generic_to_shared(vsm);
    unsigned pbm_sh = (unsigned)__cvta_generic_to_shared(pbm);
    // A: row = cb + (lane&15), col-halves by lane>>4
    unsigned a_addr_base = vsm_sh + ((cb + (lane & 15)) * 72 + ((lane >> 4) << 3)) * 2;
    // B: row = (lane&7) + 8*(lane>=16), col-halves by (lane>>3)&1
    unsigned b_row = (lane & 7) + ((lane >> 4) << 3);
    unsigned b_addr_base = pbm_sh + (b_row * 72 + (((lane >> 3) & 1) << 3)) * 2;

    float acc[8][4];
#pragma unroll
    for (int a = 0; a < 8; a++)
#pragma unroll
        for (int c = 0; c < 4; c++) acc[a][c] = 0.f;

    float* attnb = out + OUT_OFF + ((size_t)b << 24);   // b * N * N
    const __nv_bfloat16* vbat = g_v + (size_t)b*CDIM*NPOS;

    for (int t = 0; t < nt; t++) {
        int jcol0 = col0 + t * 64;
        __syncthreads();   // prev-iter MMA done reading vsm/pbm
        // ---- stage K tile (fp32) ----
        {
            const float4 kv = ((const float4*)(g_k +
                ((size_t)(b << 12) + jcol0 + (tid >> 2)) * CQD))[tid & 3];
            *(float4*)&ks[(tid >> 2) * 20 + (tid & 3) * 4] = kv;
        }
        // ---- stage V tile (bf16, vectorized 16B) ----
#pragma unroll
        for (int it = 0; it < 4; it++) {
            int idx = it * 256 + tid;           // 0..1023
            int c   = idx >> 3;
            int ch  = idx & 7;
            uint4 vv = *(const uint4*)(vbat + (size_t)c * NPOS + jcol0 + ch * 8);
            *(uint4*)(vsm + c * 72 + ch * 8) = vv;
        }
        __syncthreads();

        // ---- e-compute -> psm (fp32, normalized p) ----
#pragma unroll
        for (int jj = 0; jj < 16; jj++) {
            int j = jj * 4 + jq;
            const float4* kr = (const float4*)&ks[j * 20];
            float4 k0 = kr[0], k1 = kr[1], k2 = kr[2], k3 = kr[3];
            float e = q0.x*k0.x + q0.y*k0.y + q0.z*k0.z + q0.w*k0.w
                    + q1.x*k1.x + q1.y*k1.y + q1.z*k1.z + q1.w*k1.w
                    + q2.x*k2.x + q2.y*k2.y + q2.z*k2.z + q2.w*k2.w
                    + q3.x*k3.x + q3.y*k3.y + q3.z*k3.z + q3.w*k3.w;
            psm[i * 68 + j] = __expf(e) * inv_i;
        }
        __syncthreads();

        // ---- attention write (vectorized) + bf16 pack into pbm ----
#pragma unroll
        for (int w2 = 0; w2 < 4; w2++) {
            int idx = w2 * 256 + tid;           // 0..1023 float4 slots
            int ii  = idx >> 4;
            int jj2 = idx & 15;
            float4 p4 = *(const float4*)&psm[ii * 68 + jj2 * 4];
            *(float4*)&attnb[(size_t)(i0 + ii) * NPOS + jcol0 + jj2 * 4] = p4;
            __nv_bfloat162 lo = __float22bfloat162_rn(make_float2(p4.x, p4.y));
            __nv_bfloat162 hi = __float22bfloat162_rn(make_float2(p4.z, p4.w));
            *(__nv_bfloat162*)(pbm + ii * 72 + jj2 * 4)     = lo;
            *(__nv_bfloat162*)(pbm + ii * 72 + jj2 * 4 + 2) = hi;
        }
        __syncthreads();

        // ---- PV accumulate: bf16 m16n8k16, operands via ldmatrix ----
#pragma unroll
        for (int ks4 = 0; ks4 < 4; ks4++) {
            unsigned a0, a1, a2, a3;
            ldsm_x4(a0, a1, a2, a3, a_addr_base + (ks4 * 16) * 2);
#pragma unroll
            for (int np = 0; np < 4; np++) {
                unsigned b0, b1, b2, b3;
                ldsm_x4(b0, b1, b2, b3,
                        b_addr_base + ((np * 16) * 72 + ks4 * 16) * 2);
                mma_bf16(acc[np*2    ], a0, a1, a2, a3, b0, b1);
                mma_bf16(acc[np*2 + 1], a0, a1, a2, a3, b2, b3);
            }
        }
    }

    // store partial PV: g_Vpart[b][g][c][i0+i]
    {
        int gq = lane >> 2;
        int tig = lane & 3;
        float* vp = g_Vpart + (((size_t)b*4 + g) * CDIM) * NPOS;
#pragma unroll
        for (int ntile = 0; ntile < 8; ntile++) {
            int irow = i0 + ntile*8 + tig*2;
            *(float2*)&vp[(size_t)(cb+gq  )*NPOS + irow] = make_float2(acc[ntile][0], acc[ntile][1]);
            *(float2*)&vp[(size_t)(cb+gq+8)*NPOS + irow] = make_float2(acc[ntile][2], acc[ntile][3]);
        }
    }
}

// ======================= K6: zero-fill masked attention ======================
__global__ void __launch_bounds__(256) zerofill(float* __restrict__ out)
{
    int row = blockIdx.x;                 // 0 .. B*N-1
    int n   = row & (NPOS - 1);
    int L   = ((n >> 6) + 1) << 6;
    if (L >= NPOS) return;
    float4* dst = (float4*)(out + OUT_OFF + ((size_t)row << 12) + L);
    int cnt4 = (NPOS - L) >> 2;
    float4 z = make_float4(0.f, 0.f, 0.f, 0.f);
    for (int t = threadIdx.x; t < cnt4; t += 256) dst[t] = z;
}

// ======================= K7: finalize ========================================
__global__ void __launch_bounds__(256) finalize(
    const float* __restrict__ x, const float* __restrict__ gamma,
    float* __restrict__ out)
{
    int t = blockIdx.x * 256 + threadIdx.x;    // < B*C*N
    int n  = t & (NPOS - 1);
    int bc = t >> 12;
    int b  = bc >> 7;
    int c  = bc & 127;
    int ngg = (n >> 10) + 1;

    const float* vp = g_Vpart + ((size_t)(b*4) * CDIM + c) * NPOS + n;
    float s = 0.f;
    for (int gg = 0; gg < ngg; gg++)
        s += vp[(size_t)gg * CDIM * NPOS];
    out[t] = gamma[0] * s + x[t];
}

// ======================= launch ==============================================
extern "C" void kernel_launch(void* const* d_in, const int* in_sizes, int n_in,
                              void* d_out, int out_size)
{
    const float* x     = (const float*)d_in[0];
    const float* wq    = (const float*)d_in[1];
    const float* bq    = (const float*)d_in[2];
    const float* wk    = (const float*)d_in[3];
    const float* bk    = (const float*)d_in[4];
    const float* wv    = (const float*)d_in[5];
    const float* bv    = (const float*)d_in[6];
    const float* gamma = (const float*)d_in[7];
    float* out = (float*)d_out;

    cudaFuncSetAttribute(attn_main,
                         cudaFuncAttributeMaxDynamicSharedMemorySize, ATTN_SMEM);

    qk_proj<<<BSZ*NPOS/256, 256>>>(x, wq, bq, wk, bk);
    v_proj<<<BSZ*(NPOS/64), 256>>>(x, wv, bv);
    rowsum_k<<<BSZ*160, 256>>>();
    attn_main<<<BSZ*160, 256, ATTN_SMEM>>>(out);
    zerofill<<<BSZ*NPOS, 256>>>(out);
    finalize<<<(BSZ*CDIM*NPOS)/256, 256>>>(x, gamma, out);
}

// round 8
// speedup vs baseline: 1.7549x; 1.3618x over previous
#include <cuda_runtime.h>
#include <cuda_bf16.h>
#include <cstdint>
#include <cstddef>

#define BSZ   4
#define CDIM  128
#define CQD   16
#define NPOS  4096
#define OUT_OFF (BSZ*CDIM*NPOS)   /* 2097152 floats; attention follows */

// ----------------- device scratch (no allocation allowed) -------------------
__device__ float          g_q[BSZ*NPOS*CQD];                 // [b][n][d]
__device__ float          g_k[BSZ*NPOS*CQD];                 // [b][n][d]
__device__ __nv_bfloat16  g_v[(size_t)BSZ*CDIM*NPOS];        // [b][c][n] bf16
__device__ float          g_Spart[BSZ*4*NPOS];               // [b][g][n] partial rowsums
__device__ float          g_Vpart[(size_t)BSZ*4*CDIM*NPOS];  // [b][g][c][n] partial PV

// ----------------- helpers ---------------------------------------------------
__device__ __forceinline__ unsigned f2tf(float f) {
    unsigned r;
    asm("cvt.rna.tf32.f32 %0, %1;" : "=r"(r) : "f"(f));
    return r;
}

__device__ __forceinline__ void mma_tf32(float c[4],
                                         unsigned a0, unsigned a1, unsigned a2, unsigned a3,
                                         unsigned b0, unsigned b1) {
    asm volatile(
        "mma.sync.aligned.m16n8k8.row.col.f32.tf32.tf32.f32 "
        "{%0,%1,%2,%3},{%4,%5,%6,%7},{%8,%9},{%0,%1,%2,%3};"
        : "+f"(c[0]), "+f"(c[1]), "+f"(c[2]), "+f"(c[3])
        : "r"(a0), "r"(a1), "r"(a2), "r"(a3), "r"(b0), "r"(b1));
}

__device__ __forceinline__ void mma_bf16(float c[4],
                                         unsigned a0, unsigned a1, unsigned a2, unsigned a3,
                                         unsigned b0, unsigned b1) {
    asm volatile(
        "mma.sync.aligned.m16n8k16.row.col.f32.bf16.bf16.f32 "
        "{%0,%1,%2,%3},{%4,%5,%6,%7},{%8,%9},{%0,%1,%2,%3};"
        : "+f"(c[0]), "+f"(c[1]), "+f"(c[2]), "+f"(c[3])
        : "r"(a0), "r"(a1), "r"(a2), "r"(a3), "r"(b0), "r"(b1));
}

__device__ __forceinline__ void ldsm_x4(unsigned& r0, unsigned& r1,
                                        unsigned& r2, unsigned& r3, unsigned addr) {
    asm volatile("ldmatrix.sync.aligned.m8n8.x4.shared.b16 {%0,%1,%2,%3}, [%4];"
                 : "=r"(r0), "=r"(r1), "=r"(r2), "=r"(r3) : "r"(addr));
}

// decode work item -> (r, g), items ordered by r DESCENDING for load balance
__device__ __forceinline__ void decode_item(int item, int& r, int& g) {
    r = 63; g = item;
    while (true) {
        int ng = (r >> 4) + 1;
        if (g < ng) break;
        g -= ng; r--;
    }
}

// load q A-fragments (hi/lo tf32) from a stride-20 smem tile
__device__ __forceinline__ void load_q_frags(const float* qsm, int iw, int lr, int lk,
                                             unsigned qh[2][4], unsigned ql[2][4]) {
#pragma unroll
    for (int s = 0; s < 2; s++) {
        float f0 = qsm[(iw + lr    ) * 20 + s*8 + lk    ];
        float f1 = qsm[(iw + lr + 8) * 20 + s*8 + lk    ];
        float f2 = qsm[(iw + lr    ) * 20 + s*8 + lk + 4];
        float f3 = qsm[(iw + lr + 8) * 20 + s*8 + lk + 4];
        qh[s][0] = f2tf(f0); ql[s][0] = f2tf(f0 - __uint_as_float(qh[s][0]));
        qh[s][1] = f2tf(f1); ql[s][1] = f2tf(f1 - __uint_as_float(qh[s][1]));
        qh[s][2] = f2tf(f2); ql[s][2] = f2tf(f2 - __uint_as_float(qh[s][2]));
        qh[s][3] = f2tf(f3); ql[s][3] = f2tf(f3 - __uint_as_float(qh[s][3]));
    }
}

// ======================= K1: q,k projection (fp32) ===========================
__global__ void __launch_bounds__(256) qk_proj(
    const float* __restrict__ x,
    const float* __restrict__ wq, const float* __restrict__ bq,
    const float* __restrict__ wk, const float* __restrict__ bk)
{
    __shared__ float wqs[CQD*CDIM], wks[CQD*CDIM];
    int tid = threadIdx.x;
    for (int i = tid; i < CQD*CDIM; i += 256) { wqs[i] = wq[i]; wks[i] = wk[i]; }
    __syncthreads();

    int t = blockIdx.x * 256 + tid;          // 0 .. B*N-1
    int b = t >> 12;
    int n = t & (NPOS - 1);
    const float* xb = x + (size_t)b*CDIM*NPOS + n;

    float qa[CQD], ka[CQD];
#pragma unroll
    for (int d = 0; d < CQD; d++) { qa[d] = bq[d]; ka[d] = bk[d]; }

    for (int c = 0; c < CDIM; c++) {
        float xv = xb[(size_t)c * NPOS];
#pragma unroll
        for (int d = 0; d < CQD; d++) {
            qa[d] = fmaf(wqs[d*CDIM + c], xv, qa[d]);
            ka[d] = fmaf(wks[d*CDIM + c], xv, ka[d]);
        }
    }
    float* qo = g_q + (size_t)t * CQD;
    float* ko = g_k + (size_t)t * CQD;
#pragma unroll
    for (int d = 0; d < CQD; d++) { qo[d] = qa[d]; ko[d] = ka[d]; }
}

// ======================= K2: v projection (tf32 MMA, bf16 out) ===============
__global__ void __launch_bounds__(256) v_proj(
    const float* __restrict__ x,
    const float* __restrict__ wv, const float* __restrict__ bv)
{
    int b  = blockIdx.x >> 6;
    int n0 = (blockIdx.x & 63) << 6;
    int w    = threadIdx.x >> 5;
    int lane = threadIdx.x & 31;
    int gq   = lane >> 2;
    int tig  = lane & 3;
    int cb   = w << 4;

    float acc[8][4];
    {
        float blo = bv[cb + gq], bhi = bv[cb + gq + 8];
#pragma unroll
        for (int nt = 0; nt < 8; nt++) {
            acc[nt][0] = blo; acc[nt][1] = blo;
            acc[nt][2] = bhi; acc[nt][3] = bhi;
        }
    }

    const float* xb = x + (size_t)b*CDIM*NPOS;
    for (int k0 = 0; k0 < CDIM; k0 += 8) {
        unsigned a0 = f2tf(wv[(cb+gq  )*CDIM + k0 + tig    ]);
        unsigned a1 = f2tf(wv[(cb+gq+8)*CDIM + k0 + tig    ]);
        unsigned a2 = f2tf(wv[(cb+gq  )*CDIM + k0 + tig + 4]);
        unsigned a3 = f2tf(wv[(cb+gq+8)*CDIM + k0 + tig + 4]);
#pragma unroll
        for (int nt = 0; nt < 8; nt++) {
            unsigned b0 = f2tf(xb[(size_t)(k0+tig  )*NPOS + n0 + nt*8 + gq]);
            unsigned b1 = f2tf(xb[(size_t)(k0+tig+4)*NPOS + n0 + nt*8 + gq]);
            mma_tf32(acc[nt], a0, a1, a2, a3, b0, b1);
        }
    }

    __nv_bfloat16* vb = g_v + (size_t)b*CDIM*NPOS;
#pragma unroll
    for (int nt = 0; nt < 8; nt++) {
        int n = n0 + nt*8 + tig*2;
        *(__nv_bfloat162*)&vb[(size_t)(cb+gq  )*NPOS + n] =
            __float22bfloat162_rn(make_float2(acc[nt][0], acc[nt][1]));
        *(__nv_bfloat162*)&vb[(size_t)(cb+gq+8)*NPOS + n] =
            __float22bfloat162_rn(make_float2(acc[nt][2], acc[nt][3]));
    }
}

// ======================= K3: rowsum pass (3xTF32 MMA) ========================
__global__ void __launch_bounds__(256, 3) rowsum_k()
{
    __shared__ float ks[64*20];
    __shared__ float qsm[64*20];
    __shared__ float red[64][2];

    int b = blockIdx.x & 3;
    int item = blockIdx.x >> 2;
    int r, g; decode_item(item, r, g);

    int tid = threadIdx.x;
    int i0 = r << 6;
    int col0 = g << 10;
    int colEnd = min((r + 1) << 6, col0 + 1024);
    int nt = (colEnd - col0) >> 6;

    // stage q tile
    {
        const float4 qv = ((const float4*)(g_q +
            ((size_t)(b << 12) + i0 + (tid >> 2)) * CQD))[tid & 3];
        *(float4*)&qsm[(tid >> 2) * 20 + (tid & 3) * 4] = qv;
    }
    __syncthreads();

    int w = tid >> 5, lane = tid & 31;
    int wr = w & 3, wc = w >> 2;
    int iw = wr << 4;
    int lr = lane >> 2, lk = lane & 3;

    unsigned qh[2][4], ql[2][4];
    load_q_frags(qsm, iw, lr, lk, qh, ql);

    float rs0 = 0.f, rs1 = 0.f;

    for (int t = 0; t < nt; t++) {
        int jcol0 = col0 + t * 64;
        __syncthreads();
        {
            const float4 kv = ((const float4*)(g_k +
                ((size_t)(b << 12) + jcol0 + (tid >> 2)) * CQD))[tid & 3];
            *(float4*)&ks[(tid >> 2) * 20 + (tid & 3) * 4] = kv;
        }
        __syncthreads();

#pragma unroll
        for (int ntile = 0; ntile < 4; ntile++) {
            int j0 = (wc << 5) + (ntile << 3);
            float acc4[4] = {0.f, 0.f, 0.f, 0.f};
#pragma unroll
            for (int s = 0; s < 2; s++) {
                float f0 = ks[(j0 + lr) * 20 + s*8 + lk    ];
                float f1 = ks[(j0 + lr) * 20 + s*8 + lk + 4];
                unsigned bh0 = f2tf(f0), bh1 = f2tf(f1);
                unsigned bl0 = f2tf(f0 - __uint_as_float(bh0));
                unsigned bl1 = f2tf(f1 - __uint_as_float(bh1));
                mma_tf32(acc4, qh[s][0], qh[s][1], qh[s][2], qh[s][3], bh0, bh1);
                mma_tf32(acc4, qh[s][0], qh[s][1], qh[s][2], qh[s][3], bl0, bl1);
                mma_tf32(acc4, ql[s][0], ql[s][1], ql[s][2], ql[s][3], bh0, bh1);
            }
            rs0 += __expf(acc4[0]) + __expf(acc4[1]);
            rs1 += __expf(acc4[2]) + __expf(acc4[3]);
        }
    }

    rs0 += __shfl_xor_sync(0xffffffffu, rs0, 1);
    rs0 += __shfl_xor_sync(0xffffffffu, rs0, 2);
    rs1 += __shfl_xor_sync(0xffffffffu, rs1, 1);
    rs1 += __shfl_xor_sync(0xffffffffu, rs1, 2);
    if (lk == 0) {
        red[iw + lr    ][wc] = rs0;
        red[iw + lr + 8][wc] = rs1;
    }
    __syncthreads();
    if (tid < 64)
        g_Spart[(((size_t)b*4 + g) << 12) + i0 + tid] = red[tid][0] + red[tid][1];
}

// ======================= K5: main pass =======================================
// e via 3xTF32 MMA, attention written straight from fragments, PV via bf16 MMA.
__global__ void __launch_bounds__(256, 2) attn_main(float* __restrict__ out)
{
    __shared__ float          ks[64*20];
    __shared__ float          qsm[64*20];
    __shared__ __nv_bfloat16  vsm[128*72];
    __shared__ __nv_bfloat16  pbm[64*72];
    __shared__ float          sinv[64];

    int b = blockIdx.x & 3;
    int item = blockIdx.x >> 2;
    int r, g; decode_item(item, r, g);

    int tid = threadIdx.x;
    int i0 = r << 6;
    int col0 = g << 10;
    int colEnd = min((r + 1) << 6, col0 + 1024);
    int nt = (colEnd - col0) >> 6;
    int ngg = (r >> 4) + 1;

    if (tid < 64) {
        float s = 0.f;
        for (int gg = 0; gg < ngg; gg++)
            s += g_Spart[(((size_t)b*4 + gg) << 12) + i0 + tid];
        sinv[tid] = 1.0f / s;
    }
    // stage q tile
    {
        const float4 qv = ((const float4*)(g_q +
            ((size_t)(b << 12) + i0 + (tid >> 2)) * CQD))[tid & 3];
        *(float4*)&qsm[(tid >> 2) * 20 + (tid & 3) * 4] = qv;
    }
    __syncthreads();

    int w = tid >> 5, lane = tid & 31;
    int wr = w & 3, wc = w >> 2;
    int iw = wr << 4;                 // e-phase warp i-base
    int lr = lane >> 2, lk = lane & 3;
    int cb = w << 4;                  // PV-phase warp c-base

    float inv0 = sinv[iw + lr], inv1 = sinv[iw + lr + 8];

    unsigned qh[2][4], ql[2][4];
    load_q_frags(qsm, iw, lr, lk, qh, ql);

    // PV ldmatrix base addresses
    unsigned vsm_sh = (unsigned)__cvta_generic_to_shared(vsm);
    unsigned pbm_sh = (unsigned)__cvta_generic_to_shared(pbm);
    unsigned a_addr_base = vsm_sh + ((cb + (lane & 15)) * 72 + ((lane >> 4) << 3)) * 2;
    unsigned b_row = (lane & 7) + ((lane >> 4) << 3);
    unsigned b_addr_base = pbm_sh + (b_row * 72 + (((lane >> 3) & 1) << 3)) * 2;

    float acc[8][4];
#pragma unroll
    for (int a = 0; a < 8; a++)
#pragma unroll
        for (int c = 0; c < 4; c++) acc[a][c] = 0.f;

    float* attnb = out + OUT_OFF + ((size_t)b << 24);
    const __nv_bfloat16* vbat = g_v + (size_t)b*CDIM*NPOS;

    for (int t = 0; t < nt; t++) {
        int jcol0 = col0 + t * 64;
        __syncthreads();   // prev-iter PV done reading vsm/pbm
        // ---- stage K tile (fp32) ----
        {
            const float4 kv = ((const float4*)(g_k +
                ((size_t)(b << 12) + jcol0 + (tid >> 2)) * CQD))[tid & 3];
            *(float4*)&ks[(tid >> 2) * 20 + (tid & 3) * 4] = kv;
        }
        // ---- stage V tile (bf16, 16B vectors) ----
#pragma unroll
        for (int it = 0; it < 4; it++) {
            int idx = it * 256 + tid;           // 0..1023
            int c   = idx >> 3;
            int ch  = idx & 7;
            *(uint4*)(vsm + c * 72 + ch * 8) =
                *(const uint4*)(vbat + (size_t)c * NPOS + jcol0 + ch * 8);
        }
        __syncthreads();

        // ---- e via 3xTF32 MMA; write attn + pbm straight from fragments ----
        float* arow0 = attnb + (size_t)(i0 + iw + lr) * NPOS + jcol0;
        float* arow1 = arow0 + (size_t)8 * NPOS;
#pragma unroll
        for (int ntile = 0; ntile < 4; ntile++) {
            int j0 = (wc << 5) + (ntile << 3);
            float acc4[4] = {0.f, 0.f, 0.f, 0.f};
#pragma unroll
            for (int s = 0; s < 2; s++) {
                float f0 = ks[(j0 + lr) * 20 + s*8 + lk    ];
                float f1 = ks[(j0 + lr) * 20 + s*8 + lk + 4];
                unsigned bh0 = f2tf(f0), bh1 = f2tf(f1);
                unsigned bl0 = f2tf(f0 - __uint_as_float(bh0));
                unsigned bl1 = f2tf(f1 - __uint_as_float(bh1));
                mma_tf32(acc4, qh[s][0], qh[s][1], qh[s][2], qh[s][3], bh0, bh1);
                mma_tf32(acc4, qh[s][0], qh[s][1], qh[s][2], qh[s][3], bl0, bl1);
                mma_tf32(acc4, ql[s][0], ql[s][1], ql[s][2], ql[s][3], bh0, bh1);
            }
            float p0 = __expf(acc4[0]) * inv0;
            float p1 = __expf(acc4[1]) * inv0;
            float p2 = __expf(acc4[2]) * inv1;
            float p3 = __expf(acc4[3]) * inv1;
            int jloc = j0 + (lk << 1);
            *(float2*)(arow0 + jloc) = make_float2(p0, p1);
            *(float2*)(arow1 + jloc) = make_float2(p2, p3);
            *(__nv_bfloat162*)(pbm + (iw + lr    ) * 72 + jloc) =
                __float22bfloat162_rn(make_float2(p0, p1));
            *(__nv_bfloat162*)(pbm + (iw + lr + 8) * 72 + jloc) =
                __float22bfloat162_rn(make_float2(p2, p3));
        }
        __syncthreads();

        // ---- PV accumulate: bf16 m16n8k16, operands via ldmatrix ----
#pragma unroll
        for (int ks4 = 0; ks4 < 4; ks4++) {
            unsigned a0, a1, a2, a3;
            ldsm_x4(a0, a1, a2, a3, a_addr_base + (ks4 * 16) * 2);
#pragma unroll
            for (int np = 0; np < 4; np++) {
                unsigned b0, b1, b2, b3;
                ldsm_x4(b0, b1, b2, b3,
                        b_addr_base + ((np * 16) * 72 + ks4 * 16) * 2);
                mma_bf16(acc[np*2    ], a0, a1, a2, a3, b0, b1);
                mma_bf16(acc[np*2 + 1], a0, a1, a2, a3, b2, b3);
            }
        }
    }

    // store partial PV: g_Vpart[b][g][c][i0+i]
    {
        int gq = lane >> 2;
        int tig = lane & 3;
        float* vp = g_Vpart + (((size_t)b*4 + g) * CDIM) * NPOS;
#pragma unroll
        for (int ntile = 0; ntile < 8; ntile++) {
            int irow = i0 + ntile*8 + tig*2;
            *(float2*)&vp[(size_t)(cb+gq  )*NPOS + irow] = make_float2(acc[ntile][0], acc[ntile][1]);
            *(float2*)&vp[(size_t)(cb+gq+8)*NPOS + irow] = make_float2(acc[ntile][2], acc[ntile][3]);
        }
    }
}

// ======================= K6: zero-fill masked attention ======================
__global__ void __launch_bounds__(256) zerofill(float* __restrict__ out)
{
    int row = blockIdx.x;                 // 0 .. B*N-1
    int n   = row & (NPOS - 1);
    int L   = ((n >> 6) + 1) << 6;
    if (L >= NPOS) return;
    float4* dst = (float4*)(out + OUT_OFF + ((size_t)row << 12) + L);
    int cnt4 = (NPOS - L) >> 2;
    float4 z = make_float4(0.f, 0.f, 0.f, 0.f);
    for (int t = threadIdx.x; t < cnt4; t += 256) dst[t] = z;
}

// ======================= K7: finalize ========================================
__global__ void __launch_bounds__(256) finalize(
    const float* __restrict__ x, const float* __restrict__ gamma,
    float* __restrict__ out)
{
    int t = blockIdx.x * 256 + threadIdx.x;    // < B*C*N
    int n  = t & (NPOS - 1);
    int bc = t >> 12;
    int b  = bc >> 7;
    int c  = bc & 127;
    int ngg = (n >> 10) + 1;

    const float* vp = g_Vpart + ((size_t)(b*4) * CDIM + c) * NPOS + n;
    float s = 0.f;
    for (int gg = 0; gg < ngg; gg++)
        s += vp[(size_t)gg * CDIM * NPOS];
    out[t] = gamma[0] * s + x[t];
}

// ======================= launch ==============================================
extern "C" void kernel_launch(void* const* d_in, const int* in_sizes, int n_in,
                              void* d_out, int out_size)
{
    const float* x     = (const float*)d_in[0];
    const float* wq    = (const float*)d_in[1];
    const float* bq    = (const float*)d_in[2];
    const float* wk    = (const float*)d_in[3];
    const float* bk    = (const float*)d_in[4];
    const float* wv    = (const float*)d_in[5];
    const float* bv    = (const float*)d_in[6];
    const float* gamma = (const float*)d_in[7];
    float* out = (float*)d_out;

    qk_proj<<<BSZ*NPOS/256, 256>>>(x, wq, bq, wk, bk);
    v_proj<<<BSZ*(NPOS/64), 256>>>(x, wv, bv);
    rowsum_k<<<BSZ*160, 256>>>();
    attn_main<<<BSZ*160, 256>>>(out);
    zerofill<<<BSZ*NPOS, 256>>>(out);
    finalize<<<(BSZ*CDIM*NPOS)/256, 256>>>(x, gamma, out);
}

// round 10
// speedup vs baseline: 2.0672x; 1.1779x over previous
#include <cuda_runtime.h>
#include <cuda_bf16.h>
#include <cstdint>
#include <cstddef>

#define BSZ   4
#define CDIM  128
#define CQD   16
#define NPOS  4096
#define OUT_OFF (BSZ*CDIM*NPOS)   /* 2097152 floats; attention follows */

// ----------------- device scratch (no allocation allowed) -------------------
__device__ float          g_q[BSZ*NPOS*CQD];                 // [b][n][d]
__device__ float          g_k[BSZ*NPOS*CQD];                 // [b][n][d]
__device__ __nv_bfloat16  g_v[(size_t)BSZ*CDIM*NPOS];        // [b][c][n] bf16
__device__ float          g_Spart[BSZ*4*NPOS];               // [b][g][n] partial rowsums
__device__ float          g_Vpart[(size_t)BSZ*4*CDIM*NPOS];  // [b][g][c][n] partial PV

// ----------------- helpers ---------------------------------------------------
__device__ __forceinline__ unsigned f2tf(float f) {
    unsigned r;
    asm("cvt.rna.tf32.f32 %0, %1;" : "=r"(r) : "f"(f));
    return r;
}

__device__ __forceinline__ void mma_tf32(float c[4],
                                         unsigned a0, unsigned a1, unsigned a2, unsigned a3,
                                         unsigned b0, unsigned b1) {
    asm volatile(
        "mma.sync.aligned.m16n8k8.row.col.f32.tf32.tf32.f32 "
        "{%0,%1,%2,%3},{%4,%5,%6,%7},{%8,%9},{%0,%1,%2,%3};"
        : "+f"(c[0]), "+f"(c[1]), "+f"(c[2]), "+f"(c[3])
        : "r"(a0), "r"(a1), "r"(a2), "r"(a3), "r"(b0), "r"(b1));
}

__device__ __forceinline__ void mma_bf16(float c[4],
                                         unsigned a0, unsigned a1, unsigned a2, unsigned a3,
                                         unsigned b0, unsigned b1) {
    asm volatile(
        "mma.sync.aligned.m16n8k16.row.col.f32.bf16.bf16.f32 "
        "{%0,%1,%2,%3},{%4,%5,%6,%7},{%8,%9},{%0,%1,%2,%3};"
        : "+f"(c[0]), "+f"(c[1]), "+f"(c[2]), "+f"(c[3])
        : "r"(a0), "r"(a1), "r"(a2), "r"(a3), "r"(b0), "r"(b1));
}

__device__ __forceinline__ void ldsm_x4(unsigned& r0, unsigned& r1,
                                        unsigned& r2, unsigned& r3, unsigned addr) {
    asm volatile("ldmatrix.sync.aligned.m8n8.x4.shared.b16 {%0,%1,%2,%3}, [%4];"
                 : "=r"(r0), "=r"(r1), "=r"(r2), "=r"(r3) : "r"(addr));
}

#define CP_ASYNC16(dst, src) \
    asm volatile("cp.async.ca.shared.global [%0], [%1], 16;" \
                 :: "r"(dst), "l"(src) : "memory")
#define CP_COMMIT()  asm volatile("cp.async.commit_group;" ::: "memory")
#define CP_WAIT1()   asm volatile("cp.async.wait_group 1;" ::: "memory")
#define CP_WAIT0()   asm volatile("cp.async.wait_group 0;" ::: "memory")

// decode work item -> (r, g), items ordered by r DESCENDING for load balance
__device__ __forceinline__ void decode_item(int item, int& r, int& g) {
    r = 63; g = item;
    while (true) {
        int ng = (r >> 4) + 1;
        if (g < ng) break;
        g -= ng; r--;
    }
}

// load q A-fragments (hi/lo tf32) from a stride-20 smem tile
__device__ __forceinline__ void load_q_frags(const float* qsm, int iw, int lr, int lk,
                                             unsigned qh[2][4], unsigned ql[2][4]) {
#pragma unroll
    for (int s = 0; s < 2; s++) {
        float f0 = qsm[(iw + lr    ) * 20 + s*8 + lk    ];
        float f1 = qsm[(iw + lr + 8) * 20 + s*8 + lk    ];
        float f2 = qsm[(iw + lr    ) * 20 + s*8 + lk + 4];
        float f3 = qsm[(iw + lr + 8) * 20 + s*8 + lk + 4];
        qh[s][0] = f2tf(f0); ql[s][0] = f2tf(f0 - __uint_as_float(qh[s][0]));
        qh[s][1] = f2tf(f1); ql[s][1] = f2tf(f1 - __uint_as_float(qh[s][1]));
        qh[s][2] = f2tf(f2); ql[s][2] = f2tf(f2 - __uint_as_float(qh[s][2]));
        qh[s][3] = f2tf(f3); ql[s][3] = f2tf(f3 - __uint_as_float(qh[s][3]));
    }
}

// hi-only variant (rowsum)
__device__ __forceinline__ void load_q_frags_hi(const float* qsm, int iw, int lr, int lk,
                                                unsigned qh[2][4]) {
#pragma unroll
    for (int s = 0; s < 2; s++) {
        qh[s][0] = f2tf(qsm[(iw + lr    ) * 20 + s*8 + lk    ]);
        qh[s][1] = f2tf(qsm[(iw + lr + 8) * 20 + s*8 + lk    ]);
        qh[s][2] = f2tf(qsm[(iw + lr    ) * 20 + s*8 + lk + 4]);
        qh[s][3] = f2tf(qsm[(iw + lr + 8) * 20 + s*8 + lk + 4]);
    }
}

// ======================= K1: q,k projection (fp32) ===========================
__global__ void __launch_bounds__(256) qk_proj(
    const float* __restrict__ x,
    const float* __restrict__ wq, const float* __restrict__ bq,
    const float* __restrict__ wk, const float* __restrict__ bk)
{
    __shared__ float wqs[CQD*CDIM], wks[CQD*CDIM];
    int tid = threadIdx.x;
    for (int i = tid; i < CQD*CDIM; i += 256) { wqs[i] = wq[i]; wks[i] = wk[i]; }
    __syncthreads();

    int t = blockIdx.x * 256 + tid;          // 0 .. B*N-1
    int b = t >> 12;
    int n = t & (NPOS - 1);
    const float* xb = x + (size_t)b*CDIM*NPOS + n;

    float qa[CQD], ka[CQD];
#pragma unroll
    for (int d = 0; d < CQD; d++) { qa[d] = bq[d]; ka[d] = bk[d]; }

    for (int c = 0; c < CDIM; c++) {
        float xv = xb[(size_t)c * NPOS];
#pragma unroll
        for (int d = 0; d < CQD; d++) {
            qa[d] = fmaf(wqs[d*CDIM + c], xv, qa[d]);
            ka[d] = fmaf(wks[d*CDIM + c], xv, ka[d]);
        }
    }
    float* qo = g_q + (size_t)t * CQD;
    float* ko = g_k + (size_t)t * CQD;
#pragma unroll
    for (int d = 0; d < CQD; d++) { qo[d] = qa[d]; ko[d] = ka[d]; }
}

// ======================= K2: v projection (bf16 MMA + ldmatrix) ==============
// D[c][n] = sum_k wv[c][k] * x[k][n] + bv[c], all operands staged bf16 in smem.
//   wsm  : 128 x 136 bf16 (c rows, k-major)
//   xsmT : 64  x 136 bf16 (n rows, k-major; transposed during staging)
#define VPROJ_SMEM (128*136*2 + 64*136*2)

__global__ void __launch_bounds__(256) v_proj(
    const float* __restrict__ x,
    const float* __restrict__ wv, const float* __restrict__ bv)
{
    extern __shared__ char vsmem_raw[];
    __nv_bfloat16* wsm  = (__nv_bfloat16*)vsmem_raw;
    __nv_bfloat16* xsmT = wsm + 128*136;

    int b  = blockIdx.x >> 6;
    int n0 = (blockIdx.x & 63) << 6;
    int tid  = threadIdx.x;
    int w    = tid >> 5;
    int lane = tid & 31;
    int gq   = lane >> 2;
    int tig  = lane & 3;
    int cb   = w << 4;

    const float* xb = x + (size_t)b*CDIM*NPOS;

    // stage wv -> wsm (bf16)
#pragma unroll
    for (int it = 0; it < 16; it++) {
        int idx = it * 256 + tid;           // 0..4095
        int c  = idx >> 5;
        int kq = idx & 31;
        float4 wf = *(const float4*)(wv + c*CDIM + kq*4);
        *(__nv_bfloat162*)(wsm + c*136 + kq*4)     = __float22bfloat162_rn(make_float2(wf.x, wf.y));
        *(__nv_bfloat162*)(wsm + c*136 + kq*4 + 2) = __float22bfloat162_rn(make_float2(wf.z, wf.w));
    }
    // stage x^T -> xsmT (bf16, transposed)
#pragma unroll
    for (int it = 0; it < 8; it++) {
        int idx = it * 256 + tid;           // 0..2047
        int k  = idx >> 4;
        int nq = idx & 15;
        float4 xf = *(const float4*)(xb + (size_t)k*NPOS + n0 + nq*4);
        xsmT[(nq*4    )*136 + k] = __float2bfloat16_rn(xf.x);
        xsmT[(nq*4 + 1)*136 + k] = __float2bfloat16_rn(xf.y);
        xsmT[(nq*4 + 2)*136 + k] = __float2bfloat16_rn(xf.z);
        xsmT[(nq*4 + 3)*136 + k] = __float2bfloat16_rn(xf.w);
    }
    __syncthreads();

    float acc[8][4];
    {
        float blo = bv[cb + gq], bhi = bv[cb + gq + 8];
#pragma unroll
        for (int nt = 0; nt < 8; nt++) {
            acc[nt][0] = blo; acc[nt][1] = blo;
            acc[nt][2] = bhi; acc[nt][3] = bhi;
        }
    }

    unsigned wsm_sh  = (unsigned)__cvta_generic_to_shared(wsm);
    unsigned xsm_sh  = (unsigned)__cvta_generic_to_shared(xsmT);
    unsigned a_base  = wsm_sh + ((cb + (lane & 15)) * 136 + ((lane >> 4) << 3)) * 2;
    unsigned b_row   = (lane & 7) + ((lane >> 4) << 3);
    unsigned b_base  = xsm_sh + (b_row * 136 + (((lane >> 3) & 1) << 3)) * 2;

#pragma unroll
    for (int ks8 = 0; ks8 < 8; ks8++) {
        unsigned a0, a1, a2, a3;
        ldsm_x4(a0, a1, a2, a3, a_base + (ks8 * 16) * 2);
#pragma unroll
        for (int np = 0; np < 4; np++) {
            unsigned b0, b1, b2, b3;
            ldsm_x4(b0, b1, b2, b3, b_base + ((np * 16) * 136 + ks8 * 16) * 2);
            mma_bf16(acc[np*2    ], a0, a1, a2, a3, b0, b1);
            mma_bf16(acc[np*2 + 1], a0, a1, a2, a3, b2, b3);
        }
    }

    __nv_bfloat16* vb = g_v + (size_t)b*CDIM*NPOS;
#pragma unroll
    for (int nt = 0; nt < 8; nt++) {
        int n = n0 + nt*8 + tig*2;
        *(__nv_bfloat162*)&vb[(size_t)(cb+gq  )*NPOS + n] =
            __float22bfloat162_rn(make_float2(acc[nt][0], acc[nt][1]));
        *(__nv_bfloat162*)&vb[(size_t)(cb+gq+8)*NPOS + n] =
            __float22bfloat162_rn(make_float2(acc[nt][2], acc[nt][3]));
    }
}

// ======================= K3: rowsum pass (2xTF32 MMA, cp.async) ==============
__global__ void __launch_bounds__(256, 3) rowsum_k()
{
    __shared__ float qsm[64*20];
    __shared__ float ks2[2][64*20];
    __shared__ float red[64][2];

    int b = blockIdx.x & 3;
    int item = blockIdx.x >> 2;
    int r, g; decode_item(item, r, g);

    int tid = threadIdx.x;
    int i0 = r << 6;
    int col0 = g << 10;
    int colEnd = min((r + 1) << 6, col0 + 1024);
    int nt = (colEnd - col0) >> 6;

    const float* kbat = g_k + ((size_t)(b << 12)) * CQD;
    unsigned ks_sh0 = (unsigned)__cvta_generic_to_shared(&ks2[0][0]);
    unsigned kdst   = (tid >> 2) * 80 + (tid & 3) * 16;
    const float* ksrc_t = kbat + (size_t)(tid >> 2) * CQD + (tid & 3) * 4;

    // stage q tile
    {
        const float4 qv = ((const float4*)(g_q +
            ((size_t)(b << 12) + i0 + (tid >> 2)) * CQD))[tid & 3];
        *(float4*)&qsm[(tid >> 2) * 20 + (tid & 3) * 4] = qv;
    }
    // prologue: issue tile 0
    CP_ASYNC16(ks_sh0 + kdst, ksrc_t + (size_t)col0 * CQD);
    CP_COMMIT();
    __syncthreads();

    int w = tid >> 5, lane = tid & 31;
    int wr = w & 3, wc = w >> 2;
    int iw = wr << 4;
    int lr = lane >> 2, lk = lane & 3;

    unsigned qh[2][4];
    load_q_frags_hi(qsm, iw, lr, lk, qh);

    float rs0 = 0.f, rs1 = 0.f;

    for (int t = 0; t < nt; t++) {
        int buf = t & 1;
        if (t + 1 < nt) {
            CP_ASYNC16(ks_sh0 + (buf ^ 1) * (64*20*4) + kdst,
                       ksrc_t + (size_t)(col0 + (t+1)*64) * CQD);
            CP_COMMIT();
            CP_WAIT1();
        } else {
            CP_WAIT0();
        }
        __syncthreads();
        const float* ksb = &ks2[buf][0];

#pragma unroll
        for (int ntile = 0; ntile < 4; ntile++) {
            int j0 = (wc << 5) + (ntile << 3);
            float acc4[4] = {0.f, 0.f, 0.f, 0.f};
#pragma unroll
            for (int s = 0; s < 2; s++) {
                float f0 = ksb[(j0 + lr) * 20 + s*8 + lk    ];
                float f1 = ksb[(j0 + lr) * 20 + s*8 + lk + 4];
                unsigned bh0 = f2tf(f0), bh1 = f2tf(f1);
                unsigned bl0 = f2tf(f0 - __uint_as_float(bh0));
                unsigned bl1 = f2tf(f1 - __uint_as_float(bh1));
                mma_tf32(acc4, qh[s][0], qh[s][1], qh[s][2], qh[s][3], bh0, bh1);
                mma_tf32(acc4, qh[s][0], qh[s][1], qh[s][2], qh[s][3], bl0, bl1);
            }
            rs0 += __expf(acc4[0]) + __expf(acc4[1]);
            rs1 += __expf(acc4[2]) + __expf(acc4[3]);
        }
        __syncthreads();
    }

    rs0 += __shfl_xor_sync(0xffffffffu, rs0, 1);
    rs0 += __shfl_xor_sync(0xffffffffu, rs0, 2);
    rs1 += __shfl_xor_sync(0xffffffffu, rs1, 1);
    rs1 += __shfl_xor_sync(0xffffffffu, rs1, 2);
    if (lk == 0) {
        red[iw + lr    ][wc] = rs0;
        red[iw + lr + 8][wc] = rs1;
    }
    __syncthreads();
    if (tid < 64)
        g_Spart[(((size_t)b*4 + g) << 12) + i0 + tid] = red[tid][0] + red[tid][1];
}

// ======================= K5: main pass =======================================
// e via 3xTF32 MMA, attention written straight from fragments, PV via bf16 MMA,
// cp.async double-buffered K/V staging, fused mask-zero epilogue.
//   qsm  : 64*20 f32    5120 B
//   ks2  : 2x64*20 f32  10240 B
//   vsm2 : 2x128*72 bf16 36864 B
//   pbm  : 64*72 bf16   9216 B
//   sinv : 64 f32       256 B
#define ATTN_SMEM (5120 + 10240 + 36864 + 9216 + 256)
#define KS_BYTES  (64*20*4)
#define VS_BYTES  (128*72*2)

__global__ void __launch_bounds__(256, 2) attn_main(float* __restrict__ out)
{
    extern __shared__ char smem_raw[];
    float*          qsm  = (float*)smem_raw;
    float*          ks2  = qsm + 64*20;
    __nv_bfloat16*  vsm2 = (__nv_bfloat16*)(ks2 + 2*64*20);
    __nv_bfloat16*  pbm  = vsm2 + 2*128*72;
    float*          sinv = (float*)(pbm + 64*72);

    int b = blockIdx.x & 3;
    int item = blockIdx.x >> 2;
    int r, g; decode_item(item, r, g);

    int tid = threadIdx.x;
    int i0 = r << 6;
    int col0 = g << 10;
    int colEnd = min((r + 1) << 6, col0 + 1024);
    int nt = (colEnd - col0) >> 6;
    int ngg = (r >> 4) + 1;

    float* attnb = out + OUT_OFF + ((size_t)b << 24);
    const __nv_bfloat16* vbat = g_v + (size_t)b*CDIM*NPOS;
    const float* kbat = g_k + ((size_t)(b << 12)) * CQD;

    unsigned ks_sh = (unsigned)__cvta_generic_to_shared(ks2);
    unsigned vs_sh = (unsigned)__cvta_generic_to_shared(vsm2);
    unsigned kdst  = (tid >> 2) * 80 + (tid & 3) * 16;
    const float* ksrc_t = kbat + (size_t)(tid >> 2) * CQD + (tid & 3) * 4;
    int vc = 0, vch = 0; // per-thread V staging coords (4 chunks)

    if (tid < 64) {
        float s = 0.f;
        for (int gg = 0; gg < ngg; gg++)
            s += g_Spart[(((size_t)b*4 + gg) << 12) + i0 + tid];
        sinv[tid] = 1.0f / s;
    }
    // stage q tile
    {
        const float4 qv = ((const float4*)(g_q +
            ((size_t)(b << 12) + i0 + (tid >> 2)) * CQD))[tid & 3];
        *(float4*)&qsm[(tid >> 2) * 20 + (tid & 3) * 4] = qv;
    }
    // prologue: issue tile 0 (K + V) into buffer 0
    {
        CP_ASYNC16(ks_sh + kdst, ksrc_t + (size_t)col0 * CQD);
#pragma unroll
        for (int it = 0; it < 4; it++) {
            int idx = it * 256 + tid;
            int c = idx >> 3, ch = idx & 7;
            CP_ASYNC16(vs_sh + c*144 + ch*16, vbat + (size_t)c*NPOS + col0 + ch*8);
        }
        CP_COMMIT();
    }
    __syncthreads();

    int w = tid >> 5, lane = tid & 31;
    int wr = w & 3, wc = w >> 2;
    int iw = wr << 4;                 // e-phase warp i-base
    int lr = lane >> 2, lk = lane & 3;
    int cb = w << 4;                  // PV-phase warp c-base

    float inv0 = sinv[iw + lr], inv1 = sinv[iw + lr + 8];

    unsigned qh[2][4], ql[2][4];
    load_q_frags(qsm, iw, lr, lk, qh, ql);

    unsigned pbm_sh = (unsigned)__cvta_generic_to_shared(pbm);
    unsigned a_base = vs_sh + ((cb + (lane & 15)) * 72 + ((lane >> 4) << 3)) * 2;
    unsigned b_row  = (lane & 7) + ((lane >> 4) << 3);
    unsigned b_base = pbm_sh + (b_row * 72 + (((lane >> 3) & 1) << 3)) * 2;

    float acc[8][4];
#pragma unroll
    for (int a = 0; a < 8; a++)
#pragma unroll
        for (int c = 0; c < 4; c++) acc[a][c] = 0.f;

    for (int t = 0; t < nt; t++) {
        int buf = t & 1;
        int jcol0 = col0 + t * 64;
        __syncthreads();   // prev-iter PV done (protects vsm[buf^1] + pbm)
        if (t + 1 < nt) {
            int jc1 = jcol0 + 64;
            int off = (buf ^ 1);
            CP_ASYNC16(ks_sh + off*KS_BYTES + kdst, ksrc_t + (size_t)jc1 * CQD);
#pragma unroll
            for (int it = 0; it < 4; it++) {
                int idx = it * 256 + tid;
                int c = idx >> 3, ch = idx & 7;
                CP_ASYNC16(vs_sh + off*VS_BYTES + c*144 + ch*16,
                           vbat + (size_t)c*NPOS + jc1 + ch*8);
            }
            CP_COMMIT();
            CP_WAIT1();
        } else {
            CP_WAIT0();
        }
        __syncthreads();   // tile t visible to all

        const float* ksb = ks2 + buf * (64*20);

        // ---- e via 3xTF32 MMA; write attn + pbm straight from fragments ----
        float* arow0 = attnb + (size_t)(i0 + iw + lr) * NPOS + jcol0;
        float* arow1 = arow0 + (size_t)8 * NPOS;
#pragma unroll
        for (int ntile = 0; ntile < 4; ntile++) {
            int j0 = (wc << 5) + (ntile << 3);
            float acc4[4] = {0.f, 0.f, 0.f, 0.f};
#pragma unroll
            for (int s = 0; s < 2; s++) {
                float f0 = ksb[(j0 + lr) * 20 + s*8 + lk    ];
                float f1 = ksb[(j0 + lr) * 20 + s*8 + lk + 4];
                unsigned bh0 = f2tf(f0), bh1 = f2tf(f1);
                unsigned bl0 = f2tf(f0 - __uint_as_float(bh0));
                unsigned bl1 = f2tf(f1 - __uint_as_float(bh1));
                mma_tf32(acc4, qh[s][0], qh[s][1], qh[s][2], qh[s][3], bh0, bh1);
                mma_tf32(acc4, qh[s][0], qh[s][1], qh[s][2], qh[s][3], bl0, bl1);
                mma_tf32(acc4, ql[s][0], ql[s][1], ql[s][2], ql[s][3], bh0, bh1);
            }
            float p0 = __expf(acc4[0]) * inv0;
            float p1 = __expf(acc4[1]) * inv0;
            float p2 = __expf(acc4[2]) * inv1;
            float p3 = __expf(acc4[3]) * inv1;
            int jloc = j0 + (lk << 1);
            *(float2*)(arow0 + jloc) = make_float2(p0, p1);
            *(float2*)(arow1 + jloc) = make_float2(p2, p3);
            *(__nv_bfloat162*)(pbm + (iw + lr    ) * 72 + jloc) =
                __float22bfloat162_rn(make_float2(p0, p1));
            *(__nv_bfloat162*)(pbm + (iw + lr + 8) * 72 + jloc) =
                __float22bfloat162_rn(make_float2(p2, p3));
        }
        __syncthreads();   // pbm ready

        // ---- PV accumulate: bf16 m16n8k16, operands via ldmatrix ----
        unsigned a_buf = a_base + buf * VS_BYTES;
#pragma unroll
        for (int ks4 = 0; ks4 < 4; ks4++) {
            unsigned a0, a1, a2, a3;
            ldsm_x4(a0, a1, a2, a3, a_buf + (ks4 * 16) * 2);
#pragma unroll
            for (int np = 0; np < 4; np++) {
                unsigned b0, b1, b2, b3;
                ldsm_x4(b0, b1, b2, b3,
                        b_base + ((np * 16) * 72 + ks4 * 16) * 2);
                mma_bf16(acc[np*2    ], a0, a1, a2, a3, b0, b1);
                mma_bf16(acc[np*2 + 1], a0, a1, a2, a3, b2, b3);
            }
        }
    }

    // store partial PV: g_Vpart[b][g][c][i0+i]
    {
        int gq = lane >> 2;
        int tig = lane & 3;
        float* vp = g_Vpart + (((size_t)b*4 + g) * CDIM) * NPOS;
#pragma unroll
        for (int ntile = 0; ntile < 8; ntile++) {
            int irow = i0 + ntile*8 + tig*2;
            *(float2*)&vp[(size_t)(cb+gq  )*NPOS + irow] = make_float2(acc[ntile][0], acc[ntile][1]);
            *(float2*)&vp[(size_t)(cb+gq+8)*NPOS + irow] = make_float2(acc[ntile][2], acc[ntile][3]);
        }
    }

    // ---- fused mask-zero epilogue: rows n ≡ item (mod 160) of this batch ----
    {
        float4 z = make_float4(0.f, 0.f, 0.f, 0.f);
        for (int n = item; n < NPOS; n += 160) {
            int L = ((n >> 6) + 1) << 6;
            if (L >= NPOS) continue;
            float4* dst = (float4*)(attnb + (size_t)n * NPOS + L);
            int cnt4 = (NPOS - L) >> 2;
            for (int t4 = tid; t4 < cnt4; t4 += 256) dst[t4] = z;
        }
    }
}

// ======================= K7: finalize ========================================
__global__ void __launch_bounds__(256) finalize(
    const float* __restrict__ x, const float* __restrict__ gamma,
    float* __restrict__ out)
{
    int t = blockIdx.x * 256 + threadIdx.x;    // < B*C*N
    int n  = t & (NPOS - 1);
    int bc = t >> 12;
    int b  = bc >> 7;
    int c  = bc & 127;
    int ngg = (n >> 10) + 1;

    const float* vp = g_Vpart + ((size_t)(b*4) * CDIM + c) * NPOS + n;
    float s = 0.f;
    for (int gg = 0; gg < ngg; gg++)
        s += vp[(size_t)gg * CDIM * NPOS];
    out[t] = gamma[0] * s + x[t];
}

// ======================= launch ==============================================
extern "C" void kernel_launch(void* const* d_in, const int* in_sizes, int n_in,
                              void* d_out, int out_size)
{
    const float* x     = (const float*)d_in[0];
    const float* wq    = (const float*)d_in[1];
    const float* bq    = (const float*)d_in[2];
    const float* wk    = (const float*)d_in[3];
    const float* bk    = (const float*)d_in[4];
    const float* wv    = (const float*)d_in[5];
    const float* bv    = (const float*)d_in[6];
    const float* gamma = (const float*)d_in[7];
    float* out = (float*)d_out;

    cudaFuncSetAttribute(attn_main,
                         cudaFuncAttributeMaxDynamicSharedMemorySize, ATTN_SMEM);
    cudaFuncSetAttribute(v_proj,
                         cudaFuncAttributeMaxDynamicSharedMemorySize, VPROJ_SMEM);

    qk_proj<<<BSZ*NPOS/256, 256>>>(x, wq, bq, wk, bk);
    v_proj<<<BSZ*(NPOS/64), 256, VPROJ_SMEM>>>(x, wv, bv);
    rowsum_k<<<BSZ*160, 256>>>();
    attn_main<<<BSZ*160, 256, ATTN_SMEM>>>(out);
    finalize<<<(BSZ*CDIM*NPOS)/256, 256>>>(x, gamma, out);
}